// round 9
// baseline (speedup 1.0000x reference)
#include <cuda_runtime.h>
#include <cuda_fp16.h>
#include <cstring>

// ---------------------------------------------------------------------------
// GNN layer, SINGLE persistent kernel with software grid barriers:
//   P0: fuse weights (A|B|C = lin@{Ws,Wn,Wu}) | h->fp16 convert | dst histogram
//   B0 -> scan (block 0 only) -> B1 -> scatter (counting sort by dst) -> B2
//   -> agg (warp/node, fp16 gather, f32x2 accumulate) -> B3(+state reset)
//   -> GEMM out = [h|hp|hu] @ W^T + bias   (K=384, FFMA2)
// Grid = occupancy * numSM (host-queried) => all blocks co-resident, barriers
// are safe by construction. All phases are gridDim-stride loops.
// ---------------------------------------------------------------------------

#define F 128
#define EDGES_CAP 640000
#define SCAN_N 12288            // 256 threads * 48 elems >= n_nodes

static __device__ int     g_bar[8];                // soft barriers, self-reset
static __device__ int     g_counts[SCAN_N + 4];    // zero-init; scan re-zeroes
static __device__ int     g_cursor[SCAN_N + 4];    // excl prefix -> row ends
static __device__ int2    g_edge[EDGES_CAP];       // {src, bits(e)} dst-sorted
static __device__ __half  g_h16[SCAN_N * F];       // fp16 copy of h
static __device__ float   g_hp[SCAN_N * F];        // mean(h[src]*e)
static __device__ float   g_hu[SCAN_N * F];        // mean(h[src])
static __device__ float   g_W[F * 3 * F];          // [128][384]: [A|B|C]
static __device__ float   g_bias[F];

// bit-cast helpers (compile to MOV)
__device__ __forceinline__ __half2 u32_to_h2(unsigned u) {
    __half2 v; memcpy(&v, &u, 4); return v;
}
__device__ __forceinline__ unsigned h2_to_u32(__half2 v) {
    unsigned u; memcpy(&u, &v, 4); return u;
}
__device__ __forceinline__ unsigned long long f2_to_u64(float2 v) {
    unsigned long long u; memcpy(&u, &v, 8); return u;
}
__device__ __forceinline__ float2 u64_to_f2(unsigned long long u) {
    float2 v; memcpy(&v, &u, 8); return v;
}

// ---------------------------------------------------------------------------
// Soft grid barrier: valid because grid size == resident capacity.
// ---------------------------------------------------------------------------
__device__ __forceinline__ void soft_barrier(int idx, int G) {
    __syncthreads();
    if (threadIdx.x == 0) {
        __threadfence();
        atomicAdd(&g_bar[idx], 1);
        while (atomicAdd(&g_bar[idx], 0) < G) __nanosleep(64);
        __threadfence();
    }
    __syncthreads();
}

// Final barrier: also resets ALL barrier state for the next graph replay.
// The block whose exit-ticket is last resets; at that point every block has
// finished spinning on g_bar[idx], so plain stores are race-free.
__device__ __forceinline__ void soft_barrier_final(int idx, int exitIdx, int G) {
    __syncthreads();
    if (threadIdx.x == 0) {
        __threadfence();
        atomicAdd(&g_bar[idx], 1);
        while (atomicAdd(&g_bar[idx], 0) < G) __nanosleep(64);
        __threadfence();
        int pos = atomicAdd(&g_bar[exitIdx], 1);
        if (pos == G - 1) {
            #pragma unroll
            for (int i = 0; i < 8; i++) g_bar[i] = 0;
            __threadfence();
        }
    }
    __syncthreads();
}

// ---------------------------------------------------------------------------
// Block-0 exclusive scan over SCAN_N counts -> g_cursor; re-zeroes counts.
// ---------------------------------------------------------------------------
__device__ void scan_embedded(int tid) {
    __shared__ int wsum[8];
    int lane = tid & 31, wid = tid >> 5;

    int4* c4 = (int4*)g_counts;
    int4* k4 = (int4*)g_cursor;

    int v[48];
    int local = 0;
    #pragma unroll
    for (int q = 0; q < 12; q++) {
        int4 a = c4[tid * 12 + q];
        v[q * 4 + 0] = a.x; v[q * 4 + 1] = a.y;
        v[q * 4 + 2] = a.z; v[q * 4 + 3] = a.w;
        local += a.x + a.y + a.z + a.w;
    }

    int inc = local;
    #pragma unroll
    for (int d = 1; d < 32; d <<= 1) {
        int t = __shfl_up_sync(0xffffffffu, inc, d);
        if (lane >= d) inc += t;
    }
    if (lane == 31) wsum[wid] = inc;
    __syncthreads();
    if (tid == 0) {
        int run = 0;
        #pragma unroll
        for (int w = 0; w < 8; w++) { int t = wsum[w]; wsum[w] = run; run += t; }
    }
    __syncthreads();

    int run = wsum[wid] + (inc - local);
    int4 z = make_int4(0, 0, 0, 0);
    #pragma unroll
    for (int q = 0; q < 12; q++) {
        int4 o;
        o.x = run; run += v[q * 4 + 0];
        o.y = run; run += v[q * 4 + 1];
        o.z = run; run += v[q * 4 + 2];
        o.w = run; run += v[q * 4 + 3];
        k4[tid * 12 + q] = o;
        c4[tid * 12 + q] = z;              // self-zero for next replay
    }
}

// ---------------------------------------------------------------------------
// GEMM tile helpers (FFMA2): BM=64, BN=128, BK=16, 4x8 micro-tile, rows
// paired for fma.rn.f32x2; B duplicated {w,w} in smem.
// ---------------------------------------------------------------------------
#define BM 64
#define BK 16
#define XS_LD 68

struct GemmSmem {
    float Xs[BK][XS_LD];
    float Wdup[BK][2 * F];
};

__device__ __forceinline__ void gemm_tile(
    GemmSmem& sm, const float* __restrict__ Xp, int kl, int k0abs,
    int m0, int M, int tid, int tx, int ty, unsigned long long acc[2][8])
{
    {
        int row = tid >> 2;
        int cg  = tid & 3;
        int gr  = m0 + row;
        if (gr >= M) gr = M - 1;
        float4 v = *(const float4*)&Xp[gr * F + kl + cg * 4];
        sm.Xs[cg * 4 + 0][row] = v.x;
        sm.Xs[cg * 4 + 1][row] = v.y;
        sm.Xs[cg * 4 + 2][row] = v.z;
        sm.Xs[cg * 4 + 3][row] = v.w;
    }
    {
        int n  = tid >> 1;
        int c8 = (tid & 1) * 8;
        float4 v0 = *(const float4*)&g_W[n * (3 * F) + k0abs + c8];
        float4 v1 = *(const float4*)&g_W[n * (3 * F) + k0abs + c8 + 4];
        float wv[8] = {v0.x, v0.y, v0.z, v0.w, v1.x, v1.y, v1.z, v1.w};
        #pragma unroll
        for (int q = 0; q < 8; q++)
            *(float2*)&sm.Wdup[c8 + q][2 * n] = make_float2(wv[q], wv[q]);
    }
    __syncthreads();

    #pragma unroll
    for (int k = 0; k < BK; k++) {
        ulonglong2 a2 = *(const ulonglong2*)&sm.Xs[k][ty * 4];
        unsigned long long ap0 = a2.x, ap1 = a2.y;
        #pragma unroll
        for (int m = 0; m < 8; m++) {
            unsigned long long b2 =
                *(const unsigned long long*)&sm.Wdup[k][2 * (tx + 16 * m)];
            asm("fma.rn.f32x2 %0, %1, %2, %0;" : "+l"(acc[0][m])
                : "l"(ap0), "l"(b2));
            asm("fma.rn.f32x2 %0, %1, %2, %0;" : "+l"(acc[1][m])
                : "l"(ap1), "l"(b2));
        }
    }
    __syncthreads();
}

// ---------------------------------------------------------------------------
__global__ __launch_bounds__(256, 3) void fused_kernel(
    const float* __restrict__ h, const float* __restrict__ e,
    const int* __restrict__ src, const int* __restrict__ dst,
    const float* __restrict__ Ws_w, const float* __restrict__ Ws_b,
    const float* __restrict__ Wn_w, const float* __restrict__ Wn_b,
    const float* __restrict__ Wu_w, const float* __restrict__ Wu_b,
    const float* __restrict__ lin_w, const float* __restrict__ lin_b,
    float* __restrict__ out, int M, int E, int G)
{
    int b = blockIdx.x, tid = threadIdx.x;
    int lane = tid & 31;
    __shared__ GemmSmem sm;                 // reused by fuse (as raw floats)

    // ======================= P0a: fuse weights ============================
    float* linrow = sm.Xs[0];               // 128 floats scratch
    for (int n = b; n < F; n += G) {
        if (tid < F) linrow[tid] = lin_w[n * F + tid];
        __syncthreads();
        for (int cc = tid; cc < 3 * F; cc += 256) {
            int seg = cc >> 7, i = cc & 127;
            const float* Wp = (seg == 0) ? Ws_w : (seg == 1) ? Wn_w : Wu_w;
            float s = 0.f;
            #pragma unroll 8
            for (int j = 0; j < F; j++)
                s += linrow[j] * Wp[j * F + i];
            g_W[n * (3 * F) + cc] = s;
        }
        if (tid < 32) {
            float s = 0.f;
            #pragma unroll
            for (int m = 0; m < 4; m++) {
                int j = tid + m * 32;
                s += linrow[j] * (Ws_b[j] + Wn_b[j] + Wu_b[j]);
            }
            #pragma unroll
            for (int d = 16; d > 0; d >>= 1)
                s += __shfl_xor_sync(0xffffffffu, s, d);
            if (tid == 0) g_bias[n] = s + lin_b[n];
        }
        __syncthreads();
    }

    // ======================= P0b: h -> fp16 ===============================
    int nElem8 = (M * F) >> 3;
    for (int i = b * 256 + tid; i < nElem8; i += G * 256) {
        float4 a = *(const float4*)&h[i * 8];
        float4 c = *(const float4*)&h[i * 8 + 4];
        uint4 o;
        o.x = h2_to_u32(__floats2half2_rn(a.x, a.y));
        o.y = h2_to_u32(__floats2half2_rn(a.z, a.w));
        o.z = h2_to_u32(__floats2half2_rn(c.x, c.y));
        o.w = h2_to_u32(__floats2half2_rn(c.z, c.w));
        *(uint4*)&g_h16[i * 8] = o;
    }

    // ======================= P0c: histogram ===============================
    int nUnits = (E + 7) >> 3;
    for (int u = b * 256 + tid; u < nUnits; u += G * 256) {
        int base = u * 8;
        if (base + 7 < E) {
            int4 d0 = *(const int4*)&dst[base];
            int4 d1 = *(const int4*)&dst[base + 4];
            atomicAdd(&g_counts[d0.x], 1); atomicAdd(&g_counts[d0.y], 1);
            atomicAdd(&g_counts[d0.z], 1); atomicAdd(&g_counts[d0.w], 1);
            atomicAdd(&g_counts[d1.x], 1); atomicAdd(&g_counts[d1.y], 1);
            atomicAdd(&g_counts[d1.z], 1); atomicAdd(&g_counts[d1.w], 1);
        } else {
            for (int q = 0; q < 8; q++)
                if (base + q < E) atomicAdd(&g_counts[dst[base + q]], 1);
        }
    }

    soft_barrier(0, G);

    // ======================= P1: scan (block 0) ===========================
    if (b == 0) scan_embedded(tid);

    soft_barrier(1, G);

    // ======================= P2: scatter ==================================
    for (int u = b * 256 + tid; u < nUnits; u += G * 256) {
        int base = u * 8;
        if (base + 7 < E) {
            int4   s0 = *(const int4*)&src[base];
            int4   s1 = *(const int4*)&src[base + 4];
            int4   d0 = *(const int4*)&dst[base];
            int4   d1 = *(const int4*)&dst[base + 4];
            float4 e0 = *(const float4*)&e[base];
            float4 e1 = *(const float4*)&e[base + 4];
            int p0 = atomicAdd(&g_cursor[d0.x], 1);
            int p1 = atomicAdd(&g_cursor[d0.y], 1);
            int p2 = atomicAdd(&g_cursor[d0.z], 1);
            int p3 = atomicAdd(&g_cursor[d0.w], 1);
            g_edge[p0] = make_int2(s0.x, __float_as_int(e0.x));
            g_edge[p1] = make_int2(s0.y, __float_as_int(e0.y));
            g_edge[p2] = make_int2(s0.z, __float_as_int(e0.z));
            g_edge[p3] = make_int2(s0.w, __float_as_int(e0.w));
            int p4 = atomicAdd(&g_cursor[d1.x], 1);
            int p5 = atomicAdd(&g_cursor[d1.y], 1);
            int p6 = atomicAdd(&g_cursor[d1.z], 1);
            int p7 = atomicAdd(&g_cursor[d1.w], 1);
            g_edge[p4] = make_int2(s1.x, __float_as_int(e1.x));
            g_edge[p5] = make_int2(s1.y, __float_as_int(e1.y));
            g_edge[p6] = make_int2(s1.z, __float_as_int(e1.z));
            g_edge[p7] = make_int2(s1.w, __float_as_int(e1.w));
        } else {
            for (int q = 0; q < 8; q++) {
                int i = base + q;
                if (i < E) {
                    int pos = atomicAdd(&g_cursor[dst[i]], 1);
                    g_edge[pos] = make_int2(src[i], __float_as_int(e[i]));
                }
            }
        }
    }

    soft_barrier(2, G);

    // ======================= P3: aggregation ==============================
    // warp per node; lane owns 4 features; f32x2 packed accumulate.
    {
        const uint2* __restrict__ hrow = (const uint2*)g_h16;
        int wg = b * 8 + (tid >> 5);
        for (int node = wg; node < M; node += G * 8) {
            int beg = (node == 0) ? 0 : g_cursor[node - 1];
            int end = g_cursor[node];
            int deg = end - beg;

            unsigned long long p0 = 0, p1 = 0, u0 = 0, u1 = 0;
            unsigned long long q0 = 0, q1 = 0, w0 = 0, w1 = 0;

            int j = beg;
            for (; j + 2 <= end; j += 2) {
                int2 pe0 = g_edge[j];
                int2 pe1 = g_edge[j + 1];
                uint2 r0 = hrow[pe0.x * 32 + lane];
                uint2 r1 = hrow[pe1.x * 32 + lane];
                float ev0 = __int_as_float(pe0.y);
                float ev1 = __int_as_float(pe1.y);
                unsigned long long e20, e21;
                asm("mov.b64 %0, {%1, %1};" : "=l"(e20) : "f"(ev0));
                asm("mov.b64 %0, {%1, %1};" : "=l"(e21) : "f"(ev1));

                unsigned long long a0 = f2_to_u64(__half22float2(u32_to_h2(r0.x)));
                unsigned long long b0 = f2_to_u64(__half22float2(u32_to_h2(r0.y)));
                unsigned long long a1 = f2_to_u64(__half22float2(u32_to_h2(r1.x)));
                unsigned long long b1 = f2_to_u64(__half22float2(u32_to_h2(r1.y)));

                asm("fma.rn.f32x2 %0, %1, %2, %0;" : "+l"(p0) : "l"(a0), "l"(e20));
                asm("fma.rn.f32x2 %0, %1, %2, %0;" : "+l"(p1) : "l"(b0), "l"(e20));
                asm("add.rn.f32x2 %0, %0, %1;"     : "+l"(u0) : "l"(a0));
                asm("add.rn.f32x2 %0, %0, %1;"     : "+l"(u1) : "l"(b0));
                asm("fma.rn.f32x2 %0, %1, %2, %0;" : "+l"(q0) : "l"(a1), "l"(e21));
                asm("fma.rn.f32x2 %0, %1, %2, %0;" : "+l"(q1) : "l"(b1), "l"(e21));
                asm("add.rn.f32x2 %0, %0, %1;"     : "+l"(w0) : "l"(a1));
                asm("add.rn.f32x2 %0, %0, %1;"     : "+l"(w1) : "l"(b1));
            }
            if (j < end) {
                int2 pe = g_edge[j];
                uint2 r = hrow[pe.x * 32 + lane];
                float ev = __int_as_float(pe.y);
                unsigned long long e2;
                asm("mov.b64 %0, {%1, %1};" : "=l"(e2) : "f"(ev));
                unsigned long long a = f2_to_u64(__half22float2(u32_to_h2(r.x)));
                unsigned long long c = f2_to_u64(__half22float2(u32_to_h2(r.y)));
                asm("fma.rn.f32x2 %0, %1, %2, %0;" : "+l"(p0) : "l"(a), "l"(e2));
                asm("fma.rn.f32x2 %0, %1, %2, %0;" : "+l"(p1) : "l"(c), "l"(e2));
                asm("add.rn.f32x2 %0, %0, %1;"     : "+l"(u0) : "l"(a));
                asm("add.rn.f32x2 %0, %0, %1;"     : "+l"(u1) : "l"(c));
            }
            asm("add.rn.f32x2 %0, %0, %1;" : "+l"(p0) : "l"(q0));
            asm("add.rn.f32x2 %0, %0, %1;" : "+l"(p1) : "l"(q1));
            asm("add.rn.f32x2 %0, %0, %1;" : "+l"(u0) : "l"(w0));
            asm("add.rn.f32x2 %0, %0, %1;" : "+l"(u1) : "l"(w1));

            float inv = 1.f / (float)max(deg, 1);
            float2 fp0 = u64_to_f2(p0), fp1 = u64_to_f2(p1);
            float2 fu0 = u64_to_f2(u0), fu1 = u64_to_f2(u1);
            ((float4*)g_hp)[node * 32 + lane] =
                make_float4(fp0.x * inv, fp0.y * inv, fp1.x * inv, fp1.y * inv);
            ((float4*)g_hu)[node * 32 + lane] =
                make_float4(fu0.x * inv, fu0.y * inv, fu1.x * inv, fu1.y * inv);
        }
    }

    soft_barrier_final(3, 4, G);

    // ======================= P4: GEMM =====================================
    // out[M,128] = [h|hp|hu](Mx384) @ W^T + bias
    {
        int tx = tid & 15, ty = tid >> 4;
        int nTiles = (M + BM - 1) / BM;
        for (int t = b; t < nTiles; t += G) {
            int m0 = t * BM;
            unsigned long long acc[2][8];
            #pragma unroll
            for (int p = 0; p < 2; p++)
                #pragma unroll
                for (int m = 0; m < 8; m++) acc[p][m] = 0ull;

            for (int kt = 0; kt < 24; kt++) {
                const float* Xp = (kt < 8) ? h : (kt < 16) ? g_hp : g_hu;
                int kl = (kt & 7) * BK;
                gemm_tile(sm, Xp, kl, kt * BK, m0, M, tid, tx, ty, acc);
            }

            #pragma unroll
            for (int p = 0; p < 2; p++) {
                int r0 = m0 + ty * 4 + p * 2;
                #pragma unroll
                for (int m = 0; m < 8; m++) {
                    int col = tx + 16 * m;
                    float bv = g_bias[col];
                    float2 v = u64_to_f2(acc[p][m]);
                    if (r0 < M)     out[r0 * F + col]       = v.x + bv;
                    if (r0 + 1 < M) out[(r0 + 1) * F + col] = v.y + bv;
                }
            }
        }
    }
}

// ---------------------------------------------------------------------------
extern "C" void kernel_launch(void* const* d_in, const int* in_sizes, int n_in,
                              void* d_out, int out_size) {
    const float* h     = (const float*)d_in[0];
    const float* e     = (const float*)d_in[1];
    const int*   src   = (const int*)d_in[2];
    const int*   dst   = (const int*)d_in[3];
    const float* Ws_w  = (const float*)d_in[4];
    const float* Ws_b  = (const float*)d_in[5];
    const float* Wn_w  = (const float*)d_in[6];
    const float* Wn_b  = (const float*)d_in[7];
    const float* Wu_w  = (const float*)d_in[8];
    const float* Wu_b  = (const float*)d_in[9];
    const float* lin_w = (const float*)d_in[10];
    const float* lin_b = (const float*)d_in[11];
    float* out = (float*)d_out;

    int M = in_sizes[0] / F;
    int E = in_sizes[2];
    if (M > SCAN_N) M = SCAN_N;
    if (E > EDGES_CAP) E = EDGES_CAP;

    // Grid sized to exactly the co-resident capacity -> soft barriers are safe.
    int dev = 0, nsm = 0, occ = 0;
    cudaGetDevice(&dev);
    cudaDeviceGetAttribute(&nsm, cudaDevAttrMultiProcessorCount, dev);
    cudaOccupancyMaxActiveBlocksPerMultiprocessor(&occ, fused_kernel, 256, 0);
    if (nsm <= 0) nsm = 148;
    if (occ <= 0) occ = 1;
    int G = occ * nsm;

    fused_kernel<<<G, 256>>>(h, e, src, dst, Ws_w, Ws_b, Wn_w, Wn_b,
                             Wu_w, Wu_b, lin_w, lin_b, out, M, E, G);
}

// round 11
// speedup vs baseline: 1.1696x; 1.1696x over previous
#include <cuda_runtime.h>
#include <cuda_fp16.h>
#include <cstring>

// ---------------------------------------------------------------------------
// GNN layer:
//   out = h@A^T + mean_dst(h[src]*e)@B^T + mean_dst(h[src])@C^T + b_total
// A = lin@Ws, B = lin@Wn, C = lin@Wu folded on-device.
//
// Graph (5 kernels, 2 events) — same structure as the 123.4us best:
//   legacy: mega(fuse ∥ convert_h16 ∥ hist + embedded scan) -> scatter
//           -> agg -> gemm_pu
//   s2:     gemm_h (h@A^T + bias), forked after mega, joins before gemm_pu.
// agg rebuilt: paired-edge half-warp gather (lanes 0-15 edge j, 16-31 edge
// j+1; uint4/LDG.128 per lane), cross-half shuffle reduction at node end.
// ---------------------------------------------------------------------------

#define F 128
#define EDGES_CAP 640000
#define SCAN_N 12288            // 256 threads * 48 elems, >= n_nodes

static __device__ int     g_counts[SCAN_N + 4];    // zero-init; scan re-zeroes
static __device__ int     g_cursor[SCAN_N + 4];    // excl. prefix -> row ends
static __device__ int     g_done;                  // hist-block ticket
static __device__ int2    g_edge[EDGES_CAP];       // {src, bits(e)} sorted by dst
static __device__ uint4   g_h16v[SCAN_N * 16];     // fp16 h rows: 16 uint4/row
static __device__ float   g_hp[SCAN_N * F];        // mean(h[src]*e)
static __device__ float   g_hu[SCAN_N * F];        // mean(h[src])
static __device__ float   g_W[F * 3 * F];          // [128][384] row-major [A|B|C]
static __device__ float   g_bias[F];

// bit-cast helpers (compile to MOV)
__device__ __forceinline__ unsigned h2_to_u32(__half2 v) {
    unsigned u; memcpy(&u, &v, 4); return u;
}
__device__ __forceinline__ __half2 u32_to_h2(unsigned u) {
    __half2 v; memcpy(&v, &u, 4); return v;
}
__device__ __forceinline__ unsigned long long f2_to_u64(float2 v) {
    unsigned long long u; memcpy(&u, &v, 8); return u;
}
__device__ __forceinline__ float2 u64_to_f2(unsigned long long u) {
    float2 v; memcpy(&v, &u, 8); return v;
}

// ---------------------------------------------------------------------------
// Embedded single-block exclusive scan over SCAN_N counts -> g_cursor.
// 256 threads, 48 elems each. Also zeroes g_counts for the next replay.
// ---------------------------------------------------------------------------
__device__ void scan_embedded(int tid) {
    __shared__ int wsum[8];
    int lane = tid & 31, wid = tid >> 5;

    int4* c4 = (int4*)g_counts;
    int4* k4 = (int4*)g_cursor;

    int v[48];
    int local = 0;
    #pragma unroll
    for (int q = 0; q < 12; q++) {
        int4 a = c4[tid * 12 + q];
        v[q * 4 + 0] = a.x; v[q * 4 + 1] = a.y;
        v[q * 4 + 2] = a.z; v[q * 4 + 3] = a.w;
        local += a.x + a.y + a.z + a.w;
    }

    int inc = local;
    #pragma unroll
    for (int d = 1; d < 32; d <<= 1) {
        int t = __shfl_up_sync(0xffffffffu, inc, d);
        if (lane >= d) inc += t;
    }
    if (lane == 31) wsum[wid] = inc;
    __syncthreads();
    if (tid == 0) {
        int run = 0;
        #pragma unroll
        for (int w = 0; w < 8; w++) { int t = wsum[w]; wsum[w] = run; run += t; }
    }
    __syncthreads();

    int run = wsum[wid] + (inc - local);
    int4 z = make_int4(0, 0, 0, 0);
    #pragma unroll
    for (int q = 0; q < 12; q++) {
        int4 o;
        o.x = run; run += v[q * 4 + 0];
        o.y = run; run += v[q * 4 + 1];
        o.z = run; run += v[q * 4 + 2];
        o.w = run; run += v[q * 4 + 3];
        k4[tid * 12 + q] = o;
        c4[tid * 12 + q] = z;              // self-zero for next replay
    }
}

// ---------------------------------------------------------------------------
// Mega kernel. Block ranges:
//   [0, F)                 : fuse weights (row n = blockIdx.x)
//   [F, F+convBlocks)      : fp32 -> fp16 conversion of h
//   [F+convBlocks, ...)    : histogram of dst (8 edges/thread); the last
//                            hist block to finish runs the embedded scan.
// ---------------------------------------------------------------------------
__global__ __launch_bounds__(256) void mega_kernel(
    const float* __restrict__ lin_w, const float* __restrict__ lin_b,
    const float* __restrict__ Ws_w, const float* __restrict__ Wn_w,
    const float* __restrict__ Wu_w,
    const float* __restrict__ Ws_b, const float* __restrict__ Wn_b,
    const float* __restrict__ Wu_b,
    const float* __restrict__ h, int nElem8, int convBlocks,
    const int* __restrict__ dst, int nE, int histBlocks)
{
    int tid = threadIdx.x;
    int b = blockIdx.x;

    if (b < F) {
        // ---- fuse weights: row b of A|B|C and bias ----
        int n = b;
        __shared__ float linrow[F];
        if (tid < F) linrow[tid] = lin_w[n * F + tid];
        __syncthreads();

        for (int cc = tid; cc < 3 * F; cc += 256) {
            int seg = cc >> 7, i = cc & 127;
            const float* Wp = (seg == 0) ? Ws_w : (seg == 1) ? Wn_w : Wu_w;
            float s = 0.f;
            #pragma unroll 8
            for (int j = 0; j < F; j++)
                s += linrow[j] * Wp[j * F + i];
            g_W[n * (3 * F) + cc] = s;
        }
        if (tid < 32) {
            float s = 0.f;
            #pragma unroll
            for (int m = 0; m < 4; m++) {
                int j = tid + m * 32;
                s += linrow[j] * (Ws_b[j] + Wn_b[j] + Wu_b[j]);
            }
            #pragma unroll
            for (int d = 16; d > 0; d >>= 1)
                s += __shfl_xor_sync(0xffffffffu, s, d);
            if (tid == 0) g_bias[n] = s + lin_b[n];
        }
    } else if (b < F + convBlocks) {
        // ---- fp16 conversion ----
        int i = (b - F) * 256 + tid;
        if (i < nElem8) {
            float4 a = *(const float4*)&h[i * 8];
            float4 c = *(const float4*)&h[i * 8 + 4];
            uint4 o;
            o.x = h2_to_u32(__floats2half2_rn(a.x, a.y));
            o.y = h2_to_u32(__floats2half2_rn(a.z, a.w));
            o.z = h2_to_u32(__floats2half2_rn(c.x, c.y));
            o.w = h2_to_u32(__floats2half2_rn(c.z, c.w));
            g_h16v[i] = o;
        }
    } else {
        // ---- histogram, 8 edges/thread ----
        int hb = b - F - convBlocks;
        int base = (hb * 256 + tid) * 8;
        if (base + 7 < nE) {
            int4 d0 = *(const int4*)&dst[base];
            int4 d1 = *(const int4*)&dst[base + 4];
            atomicAdd(&g_counts[d0.x], 1); atomicAdd(&g_counts[d0.y], 1);
            atomicAdd(&g_counts[d0.z], 1); atomicAdd(&g_counts[d0.w], 1);
            atomicAdd(&g_counts[d1.x], 1); atomicAdd(&g_counts[d1.y], 1);
            atomicAdd(&g_counts[d1.z], 1); atomicAdd(&g_counts[d1.w], 1);
        } else {
            for (int q = 0; q < 8; q++)
                if (base + q < nE) atomicAdd(&g_counts[dst[base + q]], 1);
        }

        // last hist block to finish runs the scan
        __threadfence();
        __syncthreads();
        __shared__ int ticket;
        if (tid == 0) ticket = atomicAdd(&g_done, 1);
        __syncthreads();
        if (ticket == histBlocks - 1) {
            if (tid == 0) atomicExch(&g_done, 0);   // reset for next replay
            __threadfence();
            scan_embedded(tid);
        }
    }
}

// ---------------------------------------------------------------------------
__global__ __launch_bounds__(256) void scatter_kernel(
    const int* __restrict__ src, const int* __restrict__ dst,
    const float* __restrict__ e, int nE)
{
    int base = (blockIdx.x * blockDim.x + threadIdx.x) * 8;
    if (base + 7 < nE) {
        int4   s0 = *(const int4*)&src[base];
        int4   s1 = *(const int4*)&src[base + 4];
        int4   d0 = *(const int4*)&dst[base];
        int4   d1 = *(const int4*)&dst[base + 4];
        float4 e0 = *(const float4*)&e[base];
        float4 e1 = *(const float4*)&e[base + 4];
        int p0 = atomicAdd(&g_cursor[d0.x], 1);
        int p1 = atomicAdd(&g_cursor[d0.y], 1);
        int p2 = atomicAdd(&g_cursor[d0.z], 1);
        int p3 = atomicAdd(&g_cursor[d0.w], 1);
        g_edge[p0] = make_int2(s0.x, __float_as_int(e0.x));
        g_edge[p1] = make_int2(s0.y, __float_as_int(e0.y));
        g_edge[p2] = make_int2(s0.z, __float_as_int(e0.z));
        g_edge[p3] = make_int2(s0.w, __float_as_int(e0.w));
        int p4 = atomicAdd(&g_cursor[d1.x], 1);
        int p5 = atomicAdd(&g_cursor[d1.y], 1);
        int p6 = atomicAdd(&g_cursor[d1.z], 1);
        int p7 = atomicAdd(&g_cursor[d1.w], 1);
        g_edge[p4] = make_int2(s1.x, __float_as_int(e1.x));
        g_edge[p5] = make_int2(s1.y, __float_as_int(e1.y));
        g_edge[p6] = make_int2(s1.z, __float_as_int(e1.z));
        g_edge[p7] = make_int2(s1.w, __float_as_int(e1.w));
    } else {
        for (int q = 0; q < 8; q++) {
            int i = base + q;
            if (i < nE) {
                int pos = atomicAdd(&g_cursor[dst[i]], 1);
                g_edge[pos] = make_int2(src[i], __float_as_int(e[i]));
            }
        }
    }
}

// ---------------------------------------------------------------------------
// agg: one warp per node, PAIRED-EDGE HALF-WARP layout.
// Lanes 0-15 process even-offset edge, lanes 16-31 the odd one. Each lane
// gathers a uint4 (8 halves = 16B) of its edge's source row. Accumulate in
// packed f32x2. At node end, halves are combined via 64-bit shuffles; lanes
// 0-15 store hp chunks, lanes 16-31 store hu chunks.
// ---------------------------------------------------------------------------
__device__ __forceinline__ void acc_edge_u4(
    uint4 rv, unsigned long long e2,
    unsigned long long hp[4], unsigned long long hu[4])
{
    unsigned long long f0 = f2_to_u64(__half22float2(u32_to_h2(rv.x)));
    unsigned long long f1 = f2_to_u64(__half22float2(u32_to_h2(rv.y)));
    unsigned long long f2 = f2_to_u64(__half22float2(u32_to_h2(rv.z)));
    unsigned long long f3 = f2_to_u64(__half22float2(u32_to_h2(rv.w)));
    asm("fma.rn.f32x2 %0, %1, %2, %0;" : "+l"(hp[0]) : "l"(f0), "l"(e2));
    asm("fma.rn.f32x2 %0, %1, %2, %0;" : "+l"(hp[1]) : "l"(f1), "l"(e2));
    asm("fma.rn.f32x2 %0, %1, %2, %0;" : "+l"(hp[2]) : "l"(f2), "l"(e2));
    asm("fma.rn.f32x2 %0, %1, %2, %0;" : "+l"(hp[3]) : "l"(f3), "l"(e2));
    asm("add.rn.f32x2 %0, %0, %1;" : "+l"(hu[0]) : "l"(f0));
    asm("add.rn.f32x2 %0, %0, %1;" : "+l"(hu[1]) : "l"(f1));
    asm("add.rn.f32x2 %0, %0, %1;" : "+l"(hu[2]) : "l"(f2));
    asm("add.rn.f32x2 %0, %0, %1;" : "+l"(hu[3]) : "l"(f3));
}

__global__ __launch_bounds__(256) void agg_kernel(int nNodes) {
    int warp = (blockIdx.x * blockDim.x + threadIdx.x) >> 5;
    int lane = threadIdx.x & 31;
    if (warp >= nNodes) return;

    int half  = lane >> 4;          // 0: even edge, 1: odd edge
    int chunk = lane & 15;          // uint4 index within the 256B row

    int beg = (warp == 0) ? 0 : g_cursor[warp - 1];
    int end = g_cursor[warp];
    int deg = end - beg;

    unsigned long long hp[4] = {0, 0, 0, 0};
    unsigned long long hu[4] = {0, 0, 0, 0};

    int j = beg;
    // 2 pairs (4 edges) per iteration: two LDG.128 gathers in flight
    for (; j + 4 <= end; j += 4) {
        int2 pe0 = g_edge[j + 0];
        int2 pe1 = g_edge[j + 1];
        int2 pe2 = g_edge[j + 2];
        int2 pe3 = g_edge[j + 3];
        int  srcA = half ? pe1.x : pe0.x;
        int  srcB = half ? pe3.x : pe2.x;
        float evA = __int_as_float(half ? pe1.y : pe0.y);
        float evB = __int_as_float(half ? pe3.y : pe2.y);
        uint4 rvA = g_h16v[srcA * 16 + chunk];
        uint4 rvB = g_h16v[srcB * 16 + chunk];
        unsigned long long eA, eB;
        asm("mov.b64 %0, {%1, %1};" : "=l"(eA) : "f"(evA));
        asm("mov.b64 %0, {%1, %1};" : "=l"(eB) : "f"(evB));
        acc_edge_u4(rvA, eA, hp, hu);
        acc_edge_u4(rvB, eB, hp, hu);
    }
    // one remaining pair
    if (j + 2 <= end) {
        int2 pe0 = g_edge[j + 0];
        int2 pe1 = g_edge[j + 1];
        int  srcA = half ? pe1.x : pe0.x;
        float evA = __int_as_float(half ? pe1.y : pe0.y);
        uint4 rvA = g_h16v[srcA * 16 + chunk];
        unsigned long long eA;
        asm("mov.b64 %0, {%1, %1};" : "=l"(eA) : "f"(evA));
        acc_edge_u4(rvA, eA, hp, hu);
        j += 2;
    }
    // single trailing edge: lanes 0-15 only
    if (j < end) {
        int2 pe = g_edge[j];
        if (half == 0) {
            uint4 rv = g_h16v[pe.x * 16 + chunk];
            unsigned long long eA;
            float ev = __int_as_float(pe.y);
            asm("mov.b64 %0, {%1, %1};" : "=l"(eA) : "f"(ev));
            acc_edge_u4(rv, eA, hp, hu);
        }
    }

    // combine the two half-warps (same chunk, xor lane bit 4)
    #pragma unroll
    for (int q = 0; q < 4; q++) {
        unsigned long long t = __shfl_xor_sync(0xffffffffu, hp[q], 16);
        asm("add.rn.f32x2 %0, %0, %1;" : "+l"(hp[q]) : "l"(t));
        t = __shfl_xor_sync(0xffffffffu, hu[q], 16);
        asm("add.rn.f32x2 %0, %0, %1;" : "+l"(hu[q]) : "l"(t));
    }

    float inv = 1.f / (float)max(deg, 1);
    // lanes 0-15 store hp chunk; lanes 16-31 store hu chunk
    unsigned long long* accs = half ? hu : hp;
    float* dstp = half ? g_hu : g_hp;
    float2 v0 = u64_to_f2(accs[0]);
    float2 v1 = u64_to_f2(accs[1]);
    float2 v2 = u64_to_f2(accs[2]);
    float2 v3 = u64_to_f2(accs[3]);
    float4 o0 = make_float4(v0.x * inv, v0.y * inv, v1.x * inv, v1.y * inv);
    float4 o1 = make_float4(v2.x * inv, v2.y * inv, v3.x * inv, v3.y * inv);
    ((float4*)dstp)[warp * 32 + chunk * 2]     = o0;
    ((float4*)dstp)[warp * 32 + chunk * 2 + 1] = o1;
}

// ---------------------------------------------------------------------------
// FFMA2 GEMM core: BM=64, BN=128, BK=16, 256 threads, 4x8 micro-tile with
// row pairs packed for fma.rn.f32x2. B stored duplicated {w,w} in smem.
// ---------------------------------------------------------------------------
#define BM 64
#define BN 128
#define BK 16
#define XS_LD 68

struct GemmSmem {
    float Xs[BK][XS_LD];
    float Wdup[BK][2 * BN];
};

__device__ __forceinline__ void gemm_tile(
    GemmSmem& sm, const float* __restrict__ Xp, int kl, int k0abs,
    int m0, int M, int tid, int tx, int ty, unsigned long long acc[2][8])
{
    {
        int row = tid >> 2;
        int cg  = tid & 3;
        int gr  = m0 + row;
        if (gr >= M) gr = M - 1;
        float4 v = *(const float4*)&Xp[gr * F + kl + cg * 4];
        sm.Xs[cg * 4 + 0][row] = v.x;
        sm.Xs[cg * 4 + 1][row] = v.y;
        sm.Xs[cg * 4 + 2][row] = v.z;
        sm.Xs[cg * 4 + 3][row] = v.w;
    }
    {
        int n  = tid >> 1;
        int c8 = (tid & 1) * 8;
        float4 v0 = *(const float4*)&g_W[n * (3 * F) + k0abs + c8];
        float4 v1 = *(const float4*)&g_W[n * (3 * F) + k0abs + c8 + 4];
        float wv[8] = {v0.x, v0.y, v0.z, v0.w, v1.x, v1.y, v1.z, v1.w};
        #pragma unroll
        for (int q = 0; q < 8; q++)
            *(float2*)&sm.Wdup[c8 + q][2 * n] = make_float2(wv[q], wv[q]);
    }
    __syncthreads();

    #pragma unroll
    for (int k = 0; k < BK; k++) {
        ulonglong2 a2 = *(const ulonglong2*)&sm.Xs[k][ty * 4];
        unsigned long long ap0 = a2.x, ap1 = a2.y;
        #pragma unroll
        for (int m = 0; m < 8; m++) {
            unsigned long long b2 =
                *(const unsigned long long*)&sm.Wdup[k][2 * (tx + 16 * m)];
            asm("fma.rn.f32x2 %0, %1, %2, %0;" : "+l"(acc[0][m])
                : "l"(ap0), "l"(b2));
            asm("fma.rn.f32x2 %0, %1, %2, %0;" : "+l"(acc[1][m])
                : "l"(ap1), "l"(b2));
        }
    }
    __syncthreads();
}

// out = h @ A^T + bias   (seg 0 of g_W)
__global__ __launch_bounds__(256) void gemm_h_kernel(
    const float* __restrict__ h, float* __restrict__ out, int M)
{
    __shared__ GemmSmem sm;
    int tid = threadIdx.x, tx = tid & 15, ty = tid >> 4;
    int m0 = blockIdx.x * BM;

    unsigned long long acc[2][8];
    #pragma unroll
    for (int p = 0; p < 2; p++)
        #pragma unroll
        for (int m = 0; m < 8; m++) acc[p][m] = 0ull;

    for (int kt = 0; kt < 8; kt++)
        gemm_tile(sm, h, kt * BK, kt * BK, m0, M, tid, tx, ty, acc);

    #pragma unroll
    for (int p = 0; p < 2; p++) {
        int r0 = m0 + ty * 4 + p * 2;
        #pragma unroll
        for (int m = 0; m < 8; m++) {
            int col = tx + 16 * m;
            float bv = g_bias[col];
            float2 v = u64_to_f2(acc[p][m]);
            if (r0 < M)     out[r0 * F + col]       = v.x + bv;
            if (r0 + 1 < M) out[(r0 + 1) * F + col] = v.y + bv;
        }
    }
}

// out += hp @ B^T + hu @ C^T   (segs 1,2 of g_W)
__global__ __launch_bounds__(256) void gemm_pu_kernel(
    float* __restrict__ out, int M)
{
    __shared__ GemmSmem sm;
    int tid = threadIdx.x, tx = tid & 15, ty = tid >> 4;
    int m0 = blockIdx.x * BM;

    unsigned long long acc[2][8];
    #pragma unroll
    for (int p = 0; p < 2; p++)
        #pragma unroll
        for (int m = 0; m < 8; m++) acc[p][m] = 0ull;

    for (int kt = 0; kt < 16; kt++) {
        const float* Xp = (kt < 8) ? g_hp : g_hu;
        int kl = (kt & 7) * BK;
        gemm_tile(sm, Xp, kl, F + kt * BK, m0, M, tid, tx, ty, acc);
    }

    #pragma unroll
    for (int p = 0; p < 2; p++) {
        int r0 = m0 + ty * 4 + p * 2;
        #pragma unroll
        for (int m = 0; m < 8; m++) {
            int col = tx + 16 * m;
            float2 v = u64_to_f2(acc[p][m]);
            if (r0 < M)
                out[r0 * F + col] += v.x;
            if (r0 + 1 < M)
                out[(r0 + 1) * F + col] += v.y;
        }
    }
}

// ---------------------------------------------------------------------------
extern "C" void kernel_launch(void* const* d_in, const int* in_sizes, int n_in,
                              void* d_out, int out_size) {
    const float* h     = (const float*)d_in[0];
    const float* e     = (const float*)d_in[1];
    const int*   src   = (const int*)d_in[2];
    const int*   dst   = (const int*)d_in[3];
    const float* Ws_w  = (const float*)d_in[4];
    const float* Ws_b  = (const float*)d_in[5];
    const float* Wn_w  = (const float*)d_in[6];
    const float* Wn_b  = (const float*)d_in[7];
    const float* Wu_w  = (const float*)d_in[8];
    const float* Wu_b  = (const float*)d_in[9];
    const float* lin_w = (const float*)d_in[10];
    const float* lin_b = (const float*)d_in[11];
    float* out = (float*)d_out;

    int M = in_sizes[0] / F;
    int E = in_sizes[2];
    if (M > SCAN_N) M = SCAN_N;
    if (E > EDGES_CAP) E = EDGES_CAP;

    int nElem8     = (M * F) / 8;
    int convBlocks = (nElem8 + 255) / 256;
    int histBlocks = (E + 2047) / 2048;

    // Side stream + events (created fresh per call; never destroyed —
    // kernel_launch is invoked only a handful of times).
    cudaStream_t s2;
    cudaStreamCreateWithFlags(&s2, cudaStreamNonBlocking);
    cudaEvent_t evA, evB;
    cudaEventCreateWithFlags(&evA, cudaEventDisableTiming);
    cudaEventCreateWithFlags(&evB, cudaEventDisableTiming);

    // legacy: mega (fuse ∥ convert ∥ hist + embedded scan)
    mega_kernel<<<F + convBlocks + histBlocks, 256>>>(
        lin_w, lin_b, Ws_w, Wn_w, Wu_w, Ws_b, Wn_b, Wu_b,
        h, nElem8, convBlocks, dst, E, histBlocks);
    cudaEventRecord(evA, 0);

    // s2: h @ A^T + bias (needs fused weights from mega)
    cudaStreamWaitEvent(s2, evA, 0);
    gemm_h_kernel<<<(M + BM - 1) / BM, 256, 0, s2>>>(h, out, M);
    cudaEventRecord(evB, s2);

    // legacy: scatter -> agg
    scatter_kernel<<<(E + 2047) / 2048, 256>>>(src, dst, e, E);
    agg_kernel<<<(M + 7) / 8, 256>>>(M);

    // join: accumulate aggregated parts into out
    cudaStreamWaitEvent(0, evB, 0);
    gemm_pu_kernel<<<(M + BM - 1) / BM, 256>>>(out, M);
}